// round 1
// baseline (speedup 1.0000x reference)
#include <cuda_runtime.h>
#include <math.h>

// Problem constants
#define BB 2
#define SS 2048
#define DD 2048
#define HH 16
#define HDD 128
#define NDD 64
#define RR 512

// ---------------------------------------------------------------------------
// Scratch (device globals: no allocations allowed)
// ---------------------------------------------------------------------------
__device__ float g_qfull[BB * SS * DD];        // x @ wq^T            [4096,2048]
__device__ float g_ckv[BB * SS * RR];          // x @ w_kv_down^T     [4096,512]
__device__ float g_knope[BB * SS * HH * NDD];  // ckv @ w_k_up^T      [4096,1024]
__device__ float g_krope[BB * SS * 64];        // x @ w_k_rope^T      [4096,64]
__device__ float g_vflat[BB * SS * DD];        // ckv @ w_v_up^T      [4096,2048] = [b,s,h,128]
__device__ float g_Q[BB * HH * SS * HDD];      // packed Q (scaled, rope applied) [b,h,s,128]
__device__ float g_K[BB * HH * SS * HDD];      // packed K (rope applied)         [b,h,s,128]
__device__ float g_attn[BB * SS * DD];         // attention out [b,s,h*128+d]

// rope freqs: 10000^(-j/32), j=0..31 (double-precision literals, rounded to f32)
__constant__ float c_freqs[32] = {
    1.0f, 0.7498942093324559f, 0.5623413251903491f, 0.42169650342858224f,
    0.31622776601683794f, 0.23713737056616552f, 0.17782794100389228f, 0.13335214321633237f,
    0.1f, 0.07498942093324558f, 0.05623413251903491f, 0.042169650342858224f,
    0.03162277660168379f, 0.023713737056616554f, 0.01778279410038923f, 0.013335214321633237f,
    0.01f, 0.007498942093324559f, 0.005623413251903491f, 0.004216965034285822f,
    0.0031622776601683794f, 0.0023713737056616554f, 0.0017782794100389228f, 0.0013335214321633237f,
    0.001f, 0.0007498942093324559f, 0.0005623413251903491f, 0.00042169650342858224f,
    0.00031622776601683794f, 0.00023713737056616554f, 0.00017782794100389228f, 0.00013335214321633237f};

// ---------------------------------------------------------------------------
// SGEMM: C[M,N] = A[M,K] @ B[N,K]^T   (A,B row-major; weights are (out,in))
// BM=BN=128, BK=16, 256 threads, 8x8 per thread. M%128==0, K%16==0 assumed.
// ---------------------------------------------------------------------------
__global__ __launch_bounds__(256) void sgemm_nt(const float* __restrict__ A,
                                                const float* __restrict__ B,
                                                float* __restrict__ C,
                                                int M, int N, int K) {
    __shared__ float As[16][132];
    __shared__ float Bs[16][132];
    const int tid = threadIdx.x;
    const int tx = tid & 15, ty = tid >> 4;
    const int m0 = blockIdx.y * 128;
    const int n0 = blockIdx.x * 128;
    const int lr = tid >> 2;          // 0..63
    const int lc = (tid & 3) << 2;    // 0,4,8,12

    float acc[8][8];
#pragma unroll
    for (int i = 0; i < 8; i++)
#pragma unroll
        for (int j = 0; j < 8; j++) acc[i][j] = 0.0f;

    for (int k0 = 0; k0 < K; k0 += 16) {
#pragma unroll
        for (int hh = 0; hh < 2; hh++) {
            int r = lr + hh * 64;
            float4 a = *(const float4*)(A + (size_t)(m0 + r) * K + k0 + lc);
            As[lc + 0][r] = a.x; As[lc + 1][r] = a.y; As[lc + 2][r] = a.z; As[lc + 3][r] = a.w;
            float4 b = make_float4(0.f, 0.f, 0.f, 0.f);
            if (n0 + r < N) b = *(const float4*)(B + (size_t)(n0 + r) * K + k0 + lc);
            Bs[lc + 0][r] = b.x; Bs[lc + 1][r] = b.y; Bs[lc + 2][r] = b.z; Bs[lc + 3][r] = b.w;
        }
        __syncthreads();
#pragma unroll
        for (int k = 0; k < 16; k++) {
            float4 a0 = *(const float4*)&As[k][ty * 8];
            float4 a1 = *(const float4*)&As[k][ty * 8 + 4];
            float4 b0 = *(const float4*)&Bs[k][tx * 8];
            float4 b1 = *(const float4*)&Bs[k][tx * 8 + 4];
            float ar[8] = {a0.x, a0.y, a0.z, a0.w, a1.x, a1.y, a1.z, a1.w};
            float br[8] = {b0.x, b0.y, b0.z, b0.w, b1.x, b1.y, b1.z, b1.w};
#pragma unroll
            for (int i = 0; i < 8; i++)
#pragma unroll
                for (int j = 0; j < 8; j++) acc[i][j] = fmaf(ar[i], br[j], acc[i][j]);
        }
        __syncthreads();
    }
#pragma unroll
    for (int i = 0; i < 8; i++) {
        size_t row = (size_t)(m0 + ty * 8 + i);
#pragma unroll
        for (int j = 0; j < 8; j++) {
            int col = n0 + tx * 8 + j;
            if (col < N) C[row * N + col] = acc[i][j];
        }
    }
}

// ---------------------------------------------------------------------------
// Pack Q: [b,s,h*128+d] -> [b,h,s,128]; rope on dims 64..127; fold 1/sqrt(128)
// One thread per (b,h,s, pair-of-dims). 64 pairs per row.
// ---------------------------------------------------------------------------
__global__ void pack_q_kernel(const float* __restrict__ qfull, float* __restrict__ Q) {
    long idx = (long)blockIdx.x * blockDim.x + threadIdx.x;  // < B*H*S*64
    int i = (int)(idx & 63);
    long t = idx >> 6;
    int s = (int)(t & (SS - 1));
    t >>= 11;
    int h = (int)(t & (HH - 1));
    int b = (int)(t >> 4);
    const float scale = 0.08838834764831845f;  // 1/sqrt(128)
    const float* src = qfull + ((size_t)(b * SS + s)) * DD + h * HDD;
    float* dst = Q + (((size_t)(b * HH + h) * SS + s)) * HDD;
    if (i < 32) {
        dst[2 * i]     = src[2 * i] * scale;
        dst[2 * i + 1] = src[2 * i + 1] * scale;
    } else {
        int j = i - 32;
        float x0 = src[64 + 2 * j], x1 = src[64 + 2 * j + 1];
        float ang = (float)s * c_freqs[j];
        float sn, cs;
        sincosf(ang, &sn, &cs);
        dst[64 + 2 * j]     = (x0 * cs - x1 * sn) * scale;
        dst[64 + 2 * j + 1] = (x1 * cs + x0 * sn) * scale;
    }
}

// ---------------------------------------------------------------------------
// Pack K: nope from [b,s,h*64+d], rope (shared across heads) from [b,s,64]
// ---------------------------------------------------------------------------
__global__ void pack_k_kernel(const float* __restrict__ knope,
                              const float* __restrict__ krope,
                              float* __restrict__ K) {
    long idx = (long)blockIdx.x * blockDim.x + threadIdx.x;
    int i = (int)(idx & 63);
    long t = idx >> 6;
    int s = (int)(t & (SS - 1));
    t >>= 11;
    int h = (int)(t & (HH - 1));
    int b = (int)(t >> 4);
    float* dst = K + (((size_t)(b * HH + h) * SS + s)) * HDD;
    if (i < 32) {
        const float* src = knope + ((size_t)(b * SS + s)) * (HH * NDD) + h * NDD;
        dst[2 * i]     = src[2 * i];
        dst[2 * i + 1] = src[2 * i + 1];
    } else {
        int j = i - 32;
        const float* src = krope + ((size_t)(b * SS + s)) * 64;
        float x0 = src[2 * j], x1 = src[2 * j + 1];
        float ang = (float)s * c_freqs[j];
        float sn, cs;
        sincosf(ang, &sn, &cs);
        dst[64 + 2 * j]     = x0 * cs - x1 * sn;
        dst[64 + 2 * j + 1] = x1 * cs + x0 * sn;
    }
}

// ---------------------------------------------------------------------------
// Flash attention (fp32, causal). BM=BN=64, d=128, 256 threads.
// Q pre-scaled. V read directly from g_vflat [b,s,h,128].
// Output written to g_attn [b,s,h*128+d].
// ---------------------------------------------------------------------------
#define FA_SMEM ((3 * 64 * 132 + 64 * 68) * 4)

__global__ __launch_bounds__(256) void fa_kernel(const float* __restrict__ Qp,
                                                 const float* __restrict__ Kp,
                                                 const float* __restrict__ Vf,
                                                 float* __restrict__ Oo) {
    extern __shared__ float sm[];
    float* Qs = sm;                    // 64 x 132
    float* Ks = Qs + 64 * 132;         // 64 x 132
    float* Vs = Ks + 64 * 132;         // 64 x 132
    float* Ps = Vs + 64 * 132;         // 64 x 68

    const int tid = threadIdx.x;
    const int tx = tid & 15, ty = tid >> 4;
    const int bh = blockIdx.y;
    const int b = bh >> 4, h = bh & 15;
    const int qt = blockIdx.x;
    const int q0 = qt * 64;

    const float* Qbase = Qp + ((size_t)bh * SS + q0) * HDD;
    // load Q tile
    for (int e = tid; e < 64 * 32; e += 256) {
        int r = e >> 5, c4 = (e & 31) << 2;
        *(float4*)(Qs + r * 132 + c4) = *(const float4*)(Qbase + r * HDD + c4);
    }

    float m_i[4], l_i[4], O[4][8];
#pragma unroll
    for (int i = 0; i < 4; i++) {
        m_i[i] = -1e30f;
        l_i[i] = 0.0f;
#pragma unroll
        for (int j = 0; j < 8; j++) O[i][j] = 0.0f;
    }

    for (int nt = 0; nt <= qt; nt++) {
        const int n0 = nt * 64;
        const float* Kbase = Kp + ((size_t)bh * SS + n0) * HDD;
        for (int e = tid; e < 64 * 32; e += 256) {
            int r = e >> 5, c4 = (e & 31) << 2;
            *(float4*)(Ks + r * 132 + c4) = *(const float4*)(Kbase + r * HDD + c4);
            *(float4*)(Vs + r * 132 + c4) =
                *(const float4*)(Vf + ((size_t)(b * SS + n0 + r)) * DD + h * HDD + c4);
        }
        __syncthreads();

        // scores: acc[i][j] = Q[ty*4+i] . K[tx+16*j]
        float acc[4][4];
#pragma unroll
        for (int i = 0; i < 4; i++)
#pragma unroll
            for (int j = 0; j < 4; j++) acc[i][j] = 0.0f;

        for (int d4 = 0; d4 < 32; d4++) {
            float4 q4[4], k4[4];
#pragma unroll
            for (int i = 0; i < 4; i++) q4[i] = *(const float4*)(Qs + (ty * 4 + i) * 132 + d4 * 4);
#pragma unroll
            for (int j = 0; j < 4; j++) k4[j] = *(const float4*)(Ks + (tx + 16 * j) * 132 + d4 * 4);
#pragma unroll
            for (int i = 0; i < 4; i++)
#pragma unroll
                for (int j = 0; j < 4; j++) {
                    acc[i][j] = fmaf(q4[i].x, k4[j].x, acc[i][j]);
                    acc[i][j] = fmaf(q4[i].y, k4[j].y, acc[i][j]);
                    acc[i][j] = fmaf(q4[i].z, k4[j].z, acc[i][j]);
                    acc[i][j] = fmaf(q4[i].w, k4[j].w, acc[i][j]);
                }
        }

        if (nt == qt) {
#pragma unroll
            for (int i = 0; i < 4; i++)
#pragma unroll
                for (int j = 0; j < 4; j++)
                    if (n0 + tx + 16 * j > q0 + ty * 4 + i) acc[i][j] = -1e30f;
        }

        // online softmax per row (rows owned by ty-group; reduce across 16 tx lanes)
#pragma unroll
        for (int i = 0; i < 4; i++) {
            float mx = fmaxf(fmaxf(acc[i][0], acc[i][1]), fmaxf(acc[i][2], acc[i][3]));
#pragma unroll
            for (int o = 8; o >= 1; o >>= 1) mx = fmaxf(mx, __shfl_xor_sync(0xffffffffu, mx, o, 16));
            float mnew = fmaxf(m_i[i], mx);
            float corr = __expf(m_i[i] - mnew);
            float rs = 0.0f;
#pragma unroll
            for (int j = 0; j < 4; j++) {
                float p = __expf(acc[i][j] - mnew);
                acc[i][j] = p;
                rs += p;
            }
#pragma unroll
            for (int o = 8; o >= 1; o >>= 1) rs += __shfl_xor_sync(0xffffffffu, rs, o, 16);
            l_i[i] = l_i[i] * corr + rs;
            m_i[i] = mnew;
#pragma unroll
            for (int j = 0; j < 8; j++) O[i][j] *= corr;
#pragma unroll
            for (int j = 0; j < 4; j++) Ps[(ty * 4 + i) * 68 + tx + 16 * j] = acc[i][j];
        }
        __syncthreads();

        // O += P @ V : thread owns rows ty*4..+3, cols tx*8..+7
        for (int c = 0; c < 64; c++) {
            float p0 = Ps[(ty * 4 + 0) * 68 + c];
            float p1 = Ps[(ty * 4 + 1) * 68 + c];
            float p2 = Ps[(ty * 4 + 2) * 68 + c];
            float p3 = Ps[(ty * 4 + 3) * 68 + c];
            float4 v0 = *(const float4*)(Vs + c * 132 + tx * 8);
            float4 v1 = *(const float4*)(Vs + c * 132 + tx * 8 + 4);
            float vv[8] = {v0.x, v0.y, v0.z, v0.w, v1.x, v1.y, v1.z, v1.w};
#pragma unroll
            for (int j = 0; j < 8; j++) {
                O[0][j] = fmaf(p0, vv[j], O[0][j]);
                O[1][j] = fmaf(p1, vv[j], O[1][j]);
                O[2][j] = fmaf(p2, vv[j], O[2][j]);
                O[3][j] = fmaf(p3, vv[j], O[3][j]);
            }
        }
        __syncthreads();
    }

#pragma unroll
    for (int i = 0; i < 4; i++) {
        float inv = 1.0f / l_i[i];
        int row = q0 + ty * 4 + i;
        float* dst = Oo + ((size_t)(b * SS + row)) * DD + h * HDD + tx * 8;
        float4 o0 = make_float4(O[i][0] * inv, O[i][1] * inv, O[i][2] * inv, O[i][3] * inv);
        float4 o1 = make_float4(O[i][4] * inv, O[i][5] * inv, O[i][6] * inv, O[i][7] * inv);
        *(float4*)(dst) = o0;
        *(float4*)(dst + 4) = o1;
    }
}

// ---------------------------------------------------------------------------
// Launch
// ---------------------------------------------------------------------------
extern "C" void kernel_launch(void* const* d_in, const int* in_sizes, int n_in,
                              void* d_out, int out_size) {
    const float* x         = (const float*)d_in[0];
    const float* wq        = (const float*)d_in[1];
    const float* w_kv_down = (const float*)d_in[2];
    const float* w_k_up    = (const float*)d_in[3];
    const float* w_k_rope  = (const float*)d_in[4];
    const float* w_v_up    = (const float*)d_in[5];
    const float* wo        = (const float*)d_in[6];
    float* out = (float*)d_out;

    float *qfull, *ckv, *knope, *krope, *vflat, *Q, *K, *attn;
    cudaGetSymbolAddress((void**)&qfull, g_qfull);
    cudaGetSymbolAddress((void**)&ckv,   g_ckv);
    cudaGetSymbolAddress((void**)&knope, g_knope);
    cudaGetSymbolAddress((void**)&krope, g_krope);
    cudaGetSymbolAddress((void**)&vflat, g_vflat);
    cudaGetSymbolAddress((void**)&Q,     g_Q);
    cudaGetSymbolAddress((void**)&K,     g_K);
    cudaGetSymbolAddress((void**)&attn,  g_attn);

    const int M = BB * SS;  // 4096
    dim3 blk(256);

    sgemm_nt<<<dim3(DD / 128, M / 128), blk>>>(x, wq, qfull, M, DD, DD);
    sgemm_nt<<<dim3(RR / 128, M / 128), blk>>>(x, w_kv_down, ckv, M, RR, DD);
    sgemm_nt<<<dim3((HH * NDD) / 128, M / 128), blk>>>(ckv, w_k_up, knope, M, HH * NDD, RR);
    sgemm_nt<<<dim3(1, M / 128), blk>>>(x, w_k_rope, krope, M, 64, DD);
    sgemm_nt<<<dim3(DD / 128, M / 128), blk>>>(ckv, w_v_up, vflat, M, DD, RR);

    pack_q_kernel<<<(BB * HH * SS * 64) / 256, 256>>>(qfull, Q);
    pack_k_kernel<<<(BB * HH * SS * 64) / 256, 256>>>(knope, krope, K);

    cudaFuncSetAttribute(fa_kernel, cudaFuncAttributeMaxDynamicSharedMemorySize, FA_SMEM);
    fa_kernel<<<dim3(SS / 64, BB * HH), 256, FA_SMEM>>>(Q, K, vflat, attn);

    sgemm_nt<<<dim3(DD / 128, M / 128), blk>>>(attn, wo, out, M, DD, DD);
}